// round 13
// baseline (speedup 1.0000x reference)
#include <cuda_runtime.h>
#include <cuda_bf16.h>
#include <math.h>
#include <stdint.h>

#define NPTS 512
#define DDIM 128
#define NMC  64
#define DENOM 16777216.0
#define NTASK 2048
#define GRID  296

// Scratch (static device globals — no allocation allowed)
__device__ uint8_t g_Xf8[(size_t)3*NMC*NPTS*DDIM];   // 12.6MB e4m3
__device__ float   g_norm[3*NMC*NPTS];
__device__ float   g_part[2*NMC*16*DDIM];            // per-block row-sum partials, sets A/C
__device__ double  g_accum;
__device__ unsigned g_count;
__device__ int     g_minn = 0x7F800000;              // global min norm (+inf; idempotent across replays)

__device__ __forceinline__ uint32_t smem_u32(const void* p) {
    uint32_t a;
    asm("{ .reg .u64 t; cvta.to.shared.u64 t, %1; cvt.u32.u64 %0, t; }" : "=r"(a) : "l"(p));
    return a;
}

__device__ __forceinline__ void ldmatrix_x4(uint32_t* r, uint32_t addr) {
    asm volatile("ldmatrix.sync.aligned.m8n8.x4.shared.b16 {%0,%1,%2,%3}, [%4];"
                 : "=r"(r[0]), "=r"(r[1]), "=r"(r[2]), "=r"(r[3]) : "r"(addr));
}

__device__ __forceinline__ void mma_fp8(float* c, const uint32_t* a, const uint32_t* b) {
    asm volatile(
        "mma.sync.aligned.m16n8k32.row.col.f32.e4m3.e4m3.f32 "
        "{%0,%1,%2,%3}, {%4,%5,%6,%7}, {%8,%9}, {%0,%1,%2,%3};"
        : "+f"(c[0]), "+f"(c[1]), "+f"(c[2]), "+f"(c[3])
        : "r"(a[0]), "r"(a[1]), "r"(a[2]), "r"(a[3]), "r"(b[0]), "r"(b[1]));
}

// First k-step: D = A*B + 0 (C = RZ zeros) — kills per-task acc zero-MOVs.
__device__ __forceinline__ void mma_fp8_zc(float* d, const uint32_t* a, const uint32_t* b) {
    asm volatile(
        "mma.sync.aligned.m16n8k32.row.col.f32.e4m3.e4m3.f32 "
        "{%0,%1,%2,%3}, {%4,%5,%6,%7}, {%8,%9}, {%10,%11,%12,%13};"
        : "=f"(d[0]), "=f"(d[1]), "=f"(d[2]), "=f"(d[3])
        : "r"(a[0]), "r"(a[1]), "r"(a[2]), "r"(a[3]), "r"(b[0]), "r"(b[1]),
          "f"(0.0f), "f"(0.0f), "f"(0.0f), "f"(0.0f));
}

__device__ __forceinline__ void cp16(uint32_t dst, const void* src) {
    asm volatile("cp.async.cg.shared.global [%0], [%1], 16;"
                 :: "r"(dst), "l"(__cvta_generic_to_global(src)) : "memory");
}
#define CP_COMMIT() asm volatile("cp.async.commit_group;" ::: "memory")
#define CP_WAIT1()  asm volatile("cp.async.wait_group 1;"  ::: "memory")

__device__ __forceinline__ uint32_t pack4_e4m3(float x0, float x1, float x2, float x3) {
    uint16_t lo, hi;
    asm("cvt.rn.satfinite.e4m3x2.f32 %0, %1, %2;" : "=h"(lo) : "f"(x1), "f"(x0));
    asm("cvt.rn.satfinite.e4m3x2.f32 %0, %1, %2;" : "=h"(hi) : "f"(x3), "f"(x2));
    return (uint32_t)lo | ((uint32_t)hi << 16);
}

// ---- k_gen: x = mu + sigma*eps -> e4m3 X, fp32 norms, A/C row-sum partials,
// and the global min norm (for k_dist's constant certificate threshold).
__global__ __launch_bounds__(256) void k_gen(
        const float* __restrict__ mu, const float* __restrict__ sigma,
        const float* __restrict__ epsA, const float* __restrict__ epsB,
        const float* __restrict__ epsC) {
    if (blockIdx.x == 0 && threadIdx.x == 0) { g_accum = 0.0; g_count = 0u; }
    int b  = blockIdx.x;
    int s  = b / (NMC * 16);
    int m  = (b / 16) % NMC;
    int ng = b % 16;
    int tid  = threadIdx.x;
    int wid  = tid >> 5;
    int lane = tid & 31;
    int n0 = ng * 32 + wid * 4;

    const float* eps = (s == 0) ? epsA : (s == 1) ? epsB : epsC;
    float4 a[4], g[4], e[4], x[4];
    #pragma unroll
    for (int r = 0; r < 4; r++) {
        a[r] = ((const float4*)(mu    + (size_t)(s*NPTS + n0 + r)*DDIM))[lane];
        g[r] = ((const float4*)(sigma + (size_t)(s*NPTS + n0 + r)*DDIM))[lane];
        e[r] = ((const float4*)(eps   + ((size_t)m*NPTS + n0 + r)*DDIM))[lane];
    }
    float ss[4];
    size_t row0 = (size_t)(s*NMC + m)*NPTS + n0;
    #pragma unroll
    for (int r = 0; r < 4; r++) {
        x[r].x = fmaf(g[r].x, e[r].x, a[r].x);
        x[r].y = fmaf(g[r].y, e[r].y, a[r].y);
        x[r].z = fmaf(g[r].z, e[r].z, a[r].z);
        x[r].w = fmaf(g[r].w, e[r].w, a[r].w);
        ((uint32_t*)(g_Xf8 + (row0 + r)*DDIM))[lane] =
            pack4_e4m3(x[r].x, x[r].y, x[r].z, x[r].w);
        ss[r] = x[r].x*x[r].x + x[r].y*x[r].y + x[r].z*x[r].z + x[r].w*x[r].w;
    }
    #pragma unroll
    for (int o = 16; o; o >>= 1) {
        #pragma unroll
        for (int r = 0; r < 4; r++) ss[r] += __shfl_xor_sync(0xffffffffu, ss[r], o);
    }
    if (lane == 0) {
        #pragma unroll
        for (int r = 0; r < 4; r++) g_norm[row0 + r] = ss[r];
    }

    // Block-min of norms -> one RED to g_minn (positive floats: int cmp == float cmp)
    __shared__ float wmin[8];
    float m4 = fminf(fminf(ss[0], ss[1]), fminf(ss[2], ss[3]));
    if (lane == 0) wmin[wid] = m4;
    __syncthreads();
    if (tid == 0) {
        float mm = wmin[0];
        #pragma unroll
        for (int i = 1; i < 8; i++) mm = fminf(mm, wmin[i]);
        atomicMin(&g_minn, __float_as_int(mm));
    }

    if (s != 1) {   // partial row-sum vectors for the analytic pos term
        __shared__ float sx[32 * DDIM];
        #pragma unroll
        for (int r = 0; r < 4; r++)
            ((float4*)sx)[(wid*4 + r) * 32 + lane] = x[r];
        __syncthreads();
        if (tid < DDIM) {
            float acc = 0.0f;
            #pragma unroll
            for (int ww = 0; ww < 32; ww++) acc += sx[ww * DDIM + tid];
            int si = (s == 0) ? 0 : 1;
            g_part[((si*NMC + m)*16 + ng)*DDIM + tid] = acc;
        }
    }
}

// Per-buffer layout: A[0:16384) B[16384:32768) xn[32768:33280) yn[33280:33792)
#define BUFSZ 33792
#define SM_TOTAL (2*BUFSZ + 128)   // +128 for 128B alignment of buffer base

// Persistent fp8 warp-MMA Gram GEMM (neg terms). CTAs 0..63 fold in the
// analytic pos term. Zero-C first MMA (no acc MOVs); constant global
// certificate threshold (no per-task min chains).
__global__ __launch_bounds__(256, 2) void k_dist(float* __restrict__ out) {
    extern __shared__ char smem[];
    __shared__ float red[8];
    uint32_t sbr = smem_u32(smem);
    uint32_t sb  = (sbr + 127u) & ~127u;           // 128B-aligned buffer base
    char* smc = smem + (sb - sbr);
    int tid  = threadIdx.x;
    int lane = tid & 31;
    int w    = tid >> 5;
    int warp_m = w & 3;     // 4 warps over M (32 rows each)
    int warp_n = w >> 2;    // 2 warps over N (64 cols each)

    // Sound constant certificate threshold: min(px)+min(py) >= gmin - 2.
    const float thr = __int_as_float(g_minn) - 2.0f;

    // --- per-thread constant offsets ---
    const uint32_t S0 = (uint32_t)((tid >> 3) * 128 + (tid & 7) * 16);
    const uint32_t D0 = (uint32_t)((tid >> 3) * 128 +
                         (((tid & 7) ^ ((tid >> 3) & 7)) << 4));
    const uint32_t TA = (uint32_t)((warp_m * 32 + (lane & 15)) * 128 +
                         (((lane >> 4) ^ (lane & 1)) << 4) +
                         (((lane >> 1) & 3) << 5));
    const uint32_t TB = (uint32_t)((warp_n * 64 + (lane & 7) + ((lane >> 4) << 3)) * 128 +
                         ((((lane >> 3) & 1) ^ (lane & 1)) << 4) +
                         (((lane >> 1) & 3) << 5));

    auto prefetch = [&](int t, uint32_t sbuf) {
        int pp = t & 1;  int r1 = t >> 1;
        int m  = r1 & 63; int r2 = r1 >> 6;
        int bx = r2 & 3;  int by = r2 >> 2;
        const uint8_t* sX = g_Xf8 + (size_t)(64 + m) * 65536 + by * 16384 + S0;
        const uint8_t* sY = g_Xf8 + (size_t)(pp * 128 + m) * 65536 + bx * 16384 + S0;
        uint32_t dA = sbuf + D0;
        #pragma unroll
        for (int i2 = 0; i2 < 4; i2++) {
            cp16(dA + i2 * 4096,          sX + i2 * 4096);
            cp16(dA + 16384 + i2 * 4096,  sY + i2 * 4096);
        }
        if (tid < 32) {
            const float* nX = g_norm + (size_t)(64 + m) * NPTS + by * 128;
            cp16(sbuf + 32768u + tid * 16, nX + tid * 4);
        } else if (tid < 64) {
            const float* nY = g_norm + (size_t)(pp * 128 + m) * NPTS + bx * 128;
            cp16(sbuf + 33280u + (tid - 32) * 16, nY + (tid - 32) * 4);
        }
    };

    prefetch((int)blockIdx.x, sb);
    CP_COMMIT();

    // ---- pos term (exact, fp32): 512*(sum||xA||^2 + sum||xC||^2) - 2*SA.SC
    if (blockIdx.x < NMC) {
        int m = blockIdx.x;
        float u = 0.0f;
        if (tid < DDIM) {
            float sa = 0.0f, sc = 0.0f;
            #pragma unroll 4
            for (int ng = 0; ng < 16; ng++) {
                sa += g_part[((0*NMC + m)*16 + ng)*DDIM + tid];
                sc += g_part[((1*NMC + m)*16 + ng)*DDIM + tid];
            }
            u = -2.0f * sa * sc;
        }
        float ns = 0.0f;
        for (int i = tid; i < NPTS; i += 256) {
            ns += g_norm[(size_t)(0*NMC + m)*NPTS + i]
                + g_norm[(size_t)(2*NMC + m)*NPTS + i];
        }
        u = fmaf(512.0f, ns, u);
        #pragma unroll
        for (int o = 16; o; o >>= 1) u += __shfl_xor_sync(0xffffffffu, u, o);
        if (lane == 0) red[w] = u;
        __syncthreads();
        if (tid == 0) {
            float v = red[0] + red[1] + red[2] + red[3]
                    + red[4] + red[5] + red[6] + red[7];
            atomicAdd(&g_accum, (double)v);
        }
        __syncthreads();
    }

    float local = 0.0f;
    int it = 0;
    for (int t = (int)blockIdx.x; t < NTASK; t += GRID, it ^= 1) {
        int nxt = t + GRID;
        if (nxt < NTASK) prefetch(nxt, sb + (uint32_t)(it ^ 1) * BUFSZ);
        CP_COMMIT();
        CP_WAIT1();
        __syncthreads();

        uint32_t bufA = sb + (uint32_t)it * BUFSZ;
        uint32_t baseA = bufA + TA;
        uint32_t baseB = bufA + 16384u + TB;
        const float* xns = (const float*)(smc + it * BUFSZ + 32768);
        const float* yns = (const float*)(smc + it * BUFSZ + 33280);

        float acc[2][8][4];
        // Software-pipelined fragment loads; ks==0 uses zero-C MMAs (no init).
        uint32_t a[2][4], tb[2][4];
        ldmatrix_x4(tb[0], baseB);          // (ks=0, nt2=0)
        #pragma unroll
        for (int ks = 0; ks < 4; ks++) {
            const uint32_t kx = (uint32_t)(ks << 5);
            ldmatrix_x4(a[0],  baseA          ^ kx);
            ldmatrix_x4(a[1], (baseA + 2048u) ^ kx);
            #pragma unroll
            for (int nt2 = 0; nt2 < 4; nt2++) {
                const int cur = nt2 & 1, nxtb = cur ^ 1;
                if (nt2 < 3) {
                    ldmatrix_x4(tb[nxtb], (baseB + (uint32_t)(nt2 + 1) * 2048u) ^ kx);
                } else if (ks < 3) {
                    ldmatrix_x4(tb[nxtb], baseB ^ (uint32_t)((ks + 1) << 5));
                }
                if (ks == 0) {
                    mma_fp8_zc(acc[0][nt2*2],     a[0], &tb[cur][0]);
                    mma_fp8_zc(acc[0][nt2*2 + 1], a[0], &tb[cur][2]);
                    mma_fp8_zc(acc[1][nt2*2],     a[1], &tb[cur][0]);
                    mma_fp8_zc(acc[1][nt2*2 + 1], a[1], &tb[cur][2]);
                } else {
                    mma_fp8(acc[0][nt2*2],     a[0], &tb[cur][0]);
                    mma_fp8(acc[0][nt2*2 + 1], a[0], &tb[cur][2]);
                    mma_fp8(acc[1][nt2*2],     a[1], &tb[cur][0]);
                    mma_fp8(acc[1][nt2*2 + 1], a[1], &tb[cur][2]);
                }
            }
        }

        // Certificate: any relu(2-d)>0 requires acc > px_i + py_j >= thr.
        float vmax = acc[0][0][0];
        #pragma unroll
        for (int mt = 0; mt < 2; mt++)
            #pragma unroll
            for (int nt = 0; nt < 8; nt++)
                #pragma unroll
                for (int r = 0; r < 4; r++)
                    vmax = fmaxf(vmax, acc[mt][nt][r]);

        if (vmax > thr) {   // rare exact path (per-pair thresholds, exact)
            #pragma unroll
            for (int mt = 0; mt < 2; mt++) {
                int mbase = warp_m * 32 + mt * 16 + (lane >> 2);
                float px0 = fmaf(xns[mbase],     0.5f, -1.0f);
                float px1 = fmaf(xns[mbase + 8], 0.5f, -1.0f);
                #pragma unroll
                for (int nt = 0; nt < 8; nt++) {
                    int nbase = warp_n * 64 + nt * 8 + (lane & 3) * 2;
                    float py0 = fmaf(yns[nbase],     0.5f, -1.0f);
                    float py1 = fmaf(yns[nbase + 1], 0.5f, -1.0f);
                    float th[4] = {px0 + py0, px0 + py1, px1 + py0, px1 + py1};
                    #pragma unroll
                    for (int r = 0; r < 4; r++) {
                        if (acc[mt][nt][r] > th[r]) {
                            float d2 = 2.0f*(th[r] - acc[mt][nt][r]) + 4.0f;
                            float q = 2.0f - sqrtf(fmaxf(d2, 1e-12f));
                            local += q*q;
                        }
                    }
                }
            }
        }
        __syncthreads();
    }

    #pragma unroll
    for (int o = 16; o; o >>= 1) local += __shfl_xor_sync(0xffffffffu, local, o);
    if (lane == 0) red[w] = local;
    __syncthreads();
    if (tid == 0) {
        float v = red[0] + red[1] + red[2] + red[3]
                + red[4] + red[5] + red[6] + red[7];
        atomicAdd(&g_accum, (double)v);
        __threadfence();
        unsigned c = atomicAdd(&g_count, 1u);
        if (c == GRID - 1) {
            double total = atomicAdd(&g_accum, 0.0);
            out[0] = (float)(total * (1.0 / DENOM));
        }
    }
}

extern "C" void kernel_launch(void* const* d_in, const int* in_sizes, int n_in,
                              void* d_out, int out_size) {
    const float* mu    = (const float*)d_in[0];
    const float* sigma = (const float*)d_in[1];
    const float* epsA  = (const float*)d_in[2];
    const float* epsB  = (const float*)d_in[3];
    const float* epsC  = (const float*)d_in[4];
    (void)in_sizes; (void)n_in; (void)out_size;

    cudaFuncSetAttribute(k_dist, cudaFuncAttributeMaxDynamicSharedMemorySize, SM_TOTAL);

    k_gen<<<3*NMC*16, 256>>>(mu, sigma, epsA, epsB, epsC);
    k_dist<<<GRID, 256, SM_TOTAL>>>((float*)d_out);
}